// round 5
// baseline (speedup 1.0000x reference)
#include <cuda_runtime.h>
#include <cstdint>

#define N_NODES   100000
#define N_EDGES   1200000
#define NODE_DIM  64
#define NUM_LAYERS 3
#define NUM_GRAPHS 256
#define R_HID     128
#define R_OUT     32

#define NN (N_NODES * NODE_DIM)

// ---- scratch (__device__ globals: allocation-free rule) ----
__device__ float g_comb[NN];                     // (1+eps)*h + neighbor-sum
__device__ float g_h[NUM_LAYERS][NN];            // per-layer GIN outputs
__device__ float g_pool[NUM_GRAPHS * NUM_LAYERS * NODE_DIM];
__device__ int   g_cnt[N_NODES];                 // in-degree histogram
__device__ int   g_rs[N_NODES + 1];              // CSR row starts
__device__ int   g_cur[N_NODES];                 // fill cursors
__device__ int   g_csrc[N_EDGES];                // CSR src lists (grouped by dst)

// ---------------------------------------------------------------------------
// CSR build step 1: in-degree histogram (spread int REDs, cheap)
// ---------------------------------------------------------------------------
__global__ void __launch_bounds__(256)
hist_kernel(const int* __restrict__ dst)
{
    int e = blockIdx.x * 256 + threadIdx.x;
    if (e < N_EDGES) atomicAdd(&g_cnt[__ldg(&dst[e])], 1);
}

// ---------------------------------------------------------------------------
// CSR build step 2: exclusive scan of 100k counts, single block of 1024.
// Each thread owns a 98-element chunk; Hillis-Steele over 1024 partials.
// Writes row_start AND the fill cursors.
// ---------------------------------------------------------------------------
__global__ void __launch_bounds__(1024)
scan_kernel()
{
    __shared__ int ssum[1024];
    const int t = threadIdx.x;
    const int CH = (N_NODES + 1023) / 1024;   // 98
    const int base = t * CH;

    int sum = 0;
    for (int i = 0; i < CH; i++) {
        int idx = base + i;
        if (idx < N_NODES) sum += g_cnt[idx];
    }
    ssum[t] = sum;
    __syncthreads();
    for (int off = 1; off < 1024; off <<= 1) {
        int v = ssum[t];
        int u = (t >= off) ? ssum[t - off] : 0;
        __syncthreads();
        ssum[t] = v + u;
        __syncthreads();
    }
    int run = (t == 0) ? 0 : ssum[t - 1];      // exclusive prefix of my chunk
    for (int i = 0; i < CH; i++) {
        int idx = base + i;
        if (idx < N_NODES) {
            g_rs[idx]  = run;
            g_cur[idx] = run;
            run += g_cnt[idx];
        }
    }
    if (t == 1023) g_rs[N_NODES] = ssum[1023];
}

// ---------------------------------------------------------------------------
// CSR build step 3: scatter edge srcs into per-dst rows
// ---------------------------------------------------------------------------
__global__ void __launch_bounds__(256)
fill_kernel(const int* __restrict__ src, const int* __restrict__ dst)
{
    int e = blockIdx.x * 256 + threadIdx.x;
    if (e < N_EDGES) {
        int pos = atomicAdd(&g_cur[__ldg(&dst[e])], 1);
        g_csrc[pos] = __ldg(&src[e]);
    }
}

// ---------------------------------------------------------------------------
// Aggregation (gather, no atomics): comb[n] = (1+eps)*h[n] + sum_{s in N(n)} h[s]
// 16 lanes per node (one float4 each -> 256B coalesced rows), neighbor loop
// unrolled x4 with independent accumulators for MLP.
// ---------------------------------------------------------------------------
__global__ void __launch_bounds__(256)
agg_kernel(const float4* __restrict__ h4,
           const float* __restrict__ eps_l,
           float4* __restrict__ comb4)
{
    unsigned idx = blockIdx.x * 256u + threadIdx.x;
    unsigned node = idx >> 4;
    if (node >= N_NODES) return;
    unsigned lane = idx & 15u;

    const int s = __ldg(&g_rs[node]);
    const int e = __ldg(&g_rs[node + 1]);

    float4 a0 = {0.f,0.f,0.f,0.f}, a1 = a0, a2 = a0, a3 = a0;
    int j = s;
    for (; j + 4 <= e; j += 4) {
        int s0 = __ldg(&g_csrc[j + 0]);
        int s1 = __ldg(&g_csrc[j + 1]);
        int s2 = __ldg(&g_csrc[j + 2]);
        int s3 = __ldg(&g_csrc[j + 3]);
        float4 v0 = __ldg(&h4[(unsigned)s0 * 16u + lane]);
        float4 v1 = __ldg(&h4[(unsigned)s1 * 16u + lane]);
        float4 v2 = __ldg(&h4[(unsigned)s2 * 16u + lane]);
        float4 v3 = __ldg(&h4[(unsigned)s3 * 16u + lane]);
        a0.x += v0.x; a0.y += v0.y; a0.z += v0.z; a0.w += v0.w;
        a1.x += v1.x; a1.y += v1.y; a1.z += v1.z; a1.w += v1.w;
        a2.x += v2.x; a2.y += v2.y; a2.z += v2.z; a2.w += v2.w;
        a3.x += v3.x; a3.y += v3.y; a3.z += v3.z; a3.w += v3.w;
    }
    for (; j < e; j++) {
        int s0 = __ldg(&g_csrc[j]);
        float4 v0 = __ldg(&h4[(unsigned)s0 * 16u + lane]);
        a0.x += v0.x; a0.y += v0.y; a0.z += v0.z; a0.w += v0.w;
    }
    float4 acc;
    acc.x = (a0.x + a1.x) + (a2.x + a3.x);
    acc.y = (a0.y + a1.y) + (a2.y + a3.y);
    acc.z = (a0.z + a1.z) + (a2.z + a3.z);
    acc.w = (a0.w + a1.w) + (a2.w + a3.w);

    const float eps1 = 1.0f + __ldg(eps_l);
    float4 hv = __ldg(&h4[node * 16u + lane]);
    float4 o;
    o.x = fmaf(eps1, hv.x, acc.x);
    o.y = fmaf(eps1, hv.y, acc.y);
    o.z = fmaf(eps1, hv.z, acc.z);
    o.w = fmaf(eps1, hv.w, acc.w);
    comb4[node * 16u + lane] = o;
}

// ---------------------------------------------------------------------------
// GIN GEMM: h_out = relu(comb @ W + b), 128-node tile, 256 threads.
// comb tile staged TRANSPOSED in smem (pitch 132); each thread computes a
// 4-node x 8-col micro-tile: per k-step 1 LDS.128 (nodes) + 2 broadcast
// LDS.128 (W) -> 32 FFMA. Output re-staged in smem (pitch 65) for coalesced
// global stores.
// Dynamic smem: W 4096 + b 64 + sT 8448 floats = 50432 B.
// ---------------------------------------------------------------------------
__global__ void __launch_bounds__(256)
gin_kernel(const float* __restrict__ comb,
           const float* __restrict__ W,
           const float* __restrict__ b,
           float* __restrict__ h_out)
{
    extern __shared__ float sm[];
    float* sW = sm;              // [64][64]
    float* sB = sm + 4096;       // [64]
    float* sT = sB + 64;         // transposed tile [64][132] / out tile [128][65]

    const int tid = threadIdx.x;
    const int nodeBase = blockIdx.x * 128;

    for (int i = tid; i < 4096; i += 256) sW[i] = __ldg(&W[i]);
    if (tid < 64) sB[tid] = __ldg(&b[tid]);

    // load tile transposed: sT[d][nloc], pitch 132
    for (int i = tid; i < 128 * 64; i += 256) {
        int nloc = i >> 6, d = i & 63;
        int node = nodeBase + nloc;
        float v = (node < N_NODES) ? __ldg(&comb[node * 64 + d]) : 0.0f;
        sT[d * 132 + nloc] = v;
    }
    __syncthreads();

    const int lane = tid & 31;   // node group: nodes lane*4 .. +3
    const int cg   = tid >> 5;   // col group (warp-uniform): cols cg*8 .. +7

    float acc[4][8];
    #pragma unroll
    for (int n = 0; n < 4; n++)
        #pragma unroll
        for (int c = 0; c < 8; c++)
            acc[n][c] = sB[cg * 8 + c];

    const float4* sW4 = reinterpret_cast<const float4*>(sW);
    const float4* sT4 = reinterpret_cast<const float4*>(sT);

    #pragma unroll 4
    for (int k = 0; k < 64; k++) {
        float4 a  = sT4[k * 33 + lane];          // 4 node values, conflict-free
        float4 w0 = sW4[k * 16 + cg * 2];        // broadcast
        float4 w1 = sW4[k * 16 + cg * 2 + 1];    // broadcast
        float av[4] = {a.x, a.y, a.z, a.w};
        float wv[8] = {w0.x, w0.y, w0.z, w0.w, w1.x, w1.y, w1.z, w1.w};
        #pragma unroll
        for (int n = 0; n < 4; n++)
            #pragma unroll
            for (int c = 0; c < 8; c++)
                acc[n][c] = fmaf(av[n], wv[c], acc[n][c]);
    }
    __syncthreads();   // everyone done reading sT

    // stage output node-major, pitch 65, then coalesced writeout
    #pragma unroll
    for (int n = 0; n < 4; n++) {
        int nloc = lane * 4 + n;
        #pragma unroll
        for (int c = 0; c < 8; c++)
            sT[nloc * 65 + cg * 8 + c] = fmaxf(acc[n][c], 0.0f);
    }
    __syncthreads();

    for (int i = tid; i < 128 * 64; i += 256) {
        int nloc = i >> 6, d = i & 63;
        int node = nodeBase + nloc;
        if (node < N_NODES)
            h_out[node * 64 + d] = sT[nloc * 65 + d];
    }
}

// ---------------------------------------------------------------------------
// Graph pooling: graph_ids sorted -> binary search for [start,end), no atomics
// ---------------------------------------------------------------------------
__global__ void __launch_bounds__(192)
pool_kernel(const int* __restrict__ gids)
{
    const int b = blockIdx.x;
    const int j = threadIdx.x;

    int lo = 0, hi = N_NODES;
    while (lo < hi) { int m = (lo + hi) >> 1; if (__ldg(&gids[m]) < b) lo = m + 1; else hi = m; }
    const int start = lo;
    hi = N_NODES;
    while (lo < hi) { int m = (lo + hi) >> 1; if (__ldg(&gids[m]) < b + 1) lo = m + 1; else hi = m; }
    const int end = lo;

    const int l = j >> 6;
    const int d = j & 63;
    const float* __restrict__ hb = g_h[l];

    float a0 = 0.f, a1 = 0.f, a2 = 0.f, a3 = 0.f;
    int n = start;
    for (; n + 3 < end; n += 4) {
        a0 += __ldg(&hb[(n + 0) * 64 + d]);
        a1 += __ldg(&hb[(n + 1) * 64 + d]);
        a2 += __ldg(&hb[(n + 2) * 64 + d]);
        a3 += __ldg(&hb[(n + 3) * 64 + d]);
    }
    for (; n < end; n++) a0 += __ldg(&hb[n * 64 + d]);
    g_pool[b * (NUM_LAYERS * NODE_DIM) + j] = (a0 + a1) + (a2 + a3);
}

// ---------------------------------------------------------------------------
// Readout MLP: out = relu(g @ W1 + b1) @ W2 + b2
// ---------------------------------------------------------------------------
__global__ void __launch_bounds__(128)
readout_kernel(const float* __restrict__ W1, const float* __restrict__ b1,
               const float* __restrict__ W2, const float* __restrict__ b2,
               float* __restrict__ out)
{
    const int b = blockIdx.x;
    const int tid = threadIdx.x;
    __shared__ float sg[NUM_LAYERS * NODE_DIM];
    __shared__ float sh[R_HID];

    for (int i = tid; i < NUM_LAYERS * NODE_DIM; i += 128)
        sg[i] = g_pool[b * (NUM_LAYERS * NODE_DIM) + i];
    __syncthreads();

    float acc = __ldg(&b1[tid]);
    #pragma unroll 8
    for (int k = 0; k < NUM_LAYERS * NODE_DIM; k++)
        acc = fmaf(sg[k], __ldg(&W1[k * R_HID + tid]), acc);
    sh[tid] = fmaxf(acc, 0.0f);
    __syncthreads();

    if (tid < R_OUT) {
        float o = __ldg(&b2[tid]);
        #pragma unroll 8
        for (int k = 0; k < R_HID; k++)
            o = fmaf(sh[k], __ldg(&W2[k * R_OUT + tid]), o);
        out[b * R_OUT + tid] = o;
    }
}

// ---------------------------------------------------------------------------
extern "C" void kernel_launch(void* const* d_in, const int* in_sizes, int n_in,
                              void* d_out, int out_size)
{
    const float* x     = (const float*)d_in[0];
    const float* gin_W = (const float*)d_in[1];
    const float* gin_b = (const float*)d_in[2];
    const float* eps   = (const float*)d_in[3];
    const float* r_W1  = (const float*)d_in[4];
    const float* r_b1  = (const float*)d_in[5];
    const float* r_W2  = (const float*)d_in[6];
    const float* r_b2  = (const float*)d_in[7];
    const int*   src   = (const int*)d_in[8];
    const int*   dst   = (const int*)d_in[9];
    const int*   gids  = (const int*)d_in[10];
    float* out = (float*)d_out;

    void* cntp = nullptr; void* combp = nullptr; void* hsym = nullptr;
    cudaGetSymbolAddress(&cntp, g_cnt);
    cudaGetSymbolAddress(&combp, g_comb);
    cudaGetSymbolAddress(&hsym, g_h);
    float* hbase = (float*)hsym;

    const int GIN_SMEM = (4096 + 64 + 8448) * (int)sizeof(float);  // 50432 B
    cudaFuncSetAttribute(gin_kernel, cudaFuncAttributeMaxDynamicSharedMemorySize, GIN_SMEM);

    const int E_BLOCKS   = (N_EDGES + 255) / 256;        // 4688
    const int AGG_BLOCKS = (N_NODES * 16 + 255) / 256;   // 6250
    const int GIN_BLOCKS = (N_NODES + 127) / 128;        // 782

    // --- build CSR once; amortized over 3 layers ---
    cudaMemsetAsync(cntp, 0, (size_t)N_NODES * sizeof(int));
    hist_kernel<<<E_BLOCKS, 256>>>(dst);
    scan_kernel<<<1, 1024>>>();
    fill_kernel<<<E_BLOCKS, 256>>>(src, dst);

    for (int l = 0; l < NUM_LAYERS; l++) {
        const float* hin = (l == 0) ? x : (hbase + (size_t)(l - 1) * NN);
        agg_kernel<<<AGG_BLOCKS, 256>>>((const float4*)hin, eps + l, (float4*)combp);
        gin_kernel<<<GIN_BLOCKS, 256, GIN_SMEM>>>((const float*)combp,
                                                  gin_W + (size_t)l * 64 * 64,
                                                  gin_b + (size_t)l * 64,
                                                  hbase + (size_t)l * NN);
    }
    pool_kernel<<<NUM_GRAPHS, NUM_LAYERS * NODE_DIM>>>(gids);
    readout_kernel<<<NUM_GRAPHS, R_HID>>>(r_W1, r_b1, r_W2, r_b2, out);
}

// round 6
// speedup vs baseline: 1.6878x; 1.6878x over previous
#include <cuda_runtime.h>
#include <cstdint>

#define N_NODES   100000
#define N_EDGES   1200000
#define NODE_DIM  64
#define NUM_LAYERS 3
#define NUM_GRAPHS 256
#define R_HID     128
#define R_OUT     32

#define NN (N_NODES * NODE_DIM)
#define SCAN_BLOCKS ((N_NODES + 255) / 256)   // 391
#define POOL_SEG 4

// ---- scratch (__device__ globals: allocation-free rule) ----
__device__ float g_comb[NN];                       // (1+eps)*h + neighbor-sum
__device__ float g_h[NUM_LAYERS][NN];              // per-layer GIN outputs
__device__ float g_poolp[POOL_SEG][NUM_GRAPHS * NUM_LAYERS * NODE_DIM];
__device__ int   g_cnt[N_NODES];                   // in-degree histogram
__device__ int   g_rs[N_NODES + 1];                // CSR row starts
__device__ int   g_cur[N_NODES];                   // fill cursors
__device__ int   g_csrc[N_EDGES];                  // CSR src lists (grouped by dst)
__device__ int   g_bsum[SCAN_BLOCKS];              // per-block count sums
__device__ int   g_boff[SCAN_BLOCKS];              // exclusive block offsets

// ---------------------------------------------------------------------------
// CSR 1: in-degree histogram (spread int REDs)
// ---------------------------------------------------------------------------
__global__ void __launch_bounds__(256)
hist_kernel(const int* __restrict__ dst)
{
    int e = blockIdx.x * 256 + threadIdx.x;
    if (e < N_EDGES) atomicAdd(&g_cnt[__ldg(&dst[e])], 1);
}

// ---------------------------------------------------------------------------
// CSR 2a: per-block sums of 256 counts (coalesced)
// ---------------------------------------------------------------------------
__global__ void __launch_bounds__(256)
bsum_kernel()
{
    __shared__ int swarp[8];
    const int t = threadIdx.x;
    int idx = blockIdx.x * 256 + t;
    int v = (idx < N_NODES) ? g_cnt[idx] : 0;
    #pragma unroll
    for (int o = 16; o > 0; o >>= 1) v += __shfl_down_sync(0xffffffffu, v, o);
    if ((t & 31) == 0) swarp[t >> 5] = v;
    __syncthreads();
    if (t < 8) {
        int s = swarp[t];
        #pragma unroll
        for (int o = 4; o > 0; o >>= 1) s += __shfl_down_sync(0xffu, s, o);
        if (t == 0) g_bsum[blockIdx.x] = s;
    }
}

// ---------------------------------------------------------------------------
// CSR 2b: single-block scan of 391 block sums -> exclusive block offsets
// ---------------------------------------------------------------------------
__global__ void __launch_bounds__(512)
boff_kernel()
{
    __shared__ int sm[512];
    const int t = threadIdx.x;
    int v = (t < SCAN_BLOCKS) ? g_bsum[t] : 0;
    sm[t] = v;
    __syncthreads();
    for (int off = 1; off < 512; off <<= 1) {
        int u = (t >= off) ? sm[t - off] : 0;
        __syncthreads();
        sm[t] += u;
        __syncthreads();
    }
    if (t < SCAN_BLOCKS) g_boff[t] = sm[t] - v;   // exclusive
}

// ---------------------------------------------------------------------------
// CSR 2c: local block scan + offset -> row starts and cursors (coalesced)
// ---------------------------------------------------------------------------
__global__ void __launch_bounds__(256)
rs_kernel()
{
    __shared__ int sm[256];
    const int t = threadIdx.x;
    int idx = blockIdx.x * 256 + t;
    int c = (idx < N_NODES) ? g_cnt[idx] : 0;
    sm[t] = c;
    __syncthreads();
    for (int off = 1; off < 256; off <<= 1) {
        int u = (t >= off) ? sm[t - off] : 0;
        __syncthreads();
        sm[t] += u;
        __syncthreads();
    }
    if (idx < N_NODES) {
        int pos = g_boff[blockIdx.x] + sm[t] - c;  // exclusive prefix
        g_rs[idx]  = pos;
        g_cur[idx] = pos;
        if (idx == N_NODES - 1) g_rs[N_NODES] = pos + c;
    }
}

// ---------------------------------------------------------------------------
// CSR 3: scatter edge srcs into per-dst rows
// ---------------------------------------------------------------------------
__global__ void __launch_bounds__(256)
fill_kernel(const int* __restrict__ src, const int* __restrict__ dst)
{
    int e = blockIdx.x * 256 + threadIdx.x;
    if (e < N_EDGES) {
        int pos = atomicAdd(&g_cur[__ldg(&dst[e])], 1);
        g_csrc[pos] = __ldg(&src[e]);
    }
}

// ---------------------------------------------------------------------------
// Aggregation (gather): comb[n] = (1+eps)*h[n] + sum_{s in N(n)} h[s]
// 16 lanes/node (one float4 each -> 256B coalesced rows), x4 unroll for MLP.
// ---------------------------------------------------------------------------
__global__ void __launch_bounds__(256)
agg_kernel(const float4* __restrict__ h4,
           const float* __restrict__ eps_l,
           float4* __restrict__ comb4)
{
    unsigned idx = blockIdx.x * 256u + threadIdx.x;
    unsigned node = idx >> 4;
    if (node >= N_NODES) return;
    unsigned lane = idx & 15u;

    const int s = __ldg(&g_rs[node]);
    const int e = __ldg(&g_rs[node + 1]);

    float4 a0 = {0.f,0.f,0.f,0.f}, a1 = a0, a2 = a0, a3 = a0;
    int j = s;
    for (; j + 4 <= e; j += 4) {
        int s0 = __ldg(&g_csrc[j + 0]);
        int s1 = __ldg(&g_csrc[j + 1]);
        int s2 = __ldg(&g_csrc[j + 2]);
        int s3 = __ldg(&g_csrc[j + 3]);
        float4 v0 = __ldg(&h4[(unsigned)s0 * 16u + lane]);
        float4 v1 = __ldg(&h4[(unsigned)s1 * 16u + lane]);
        float4 v2 = __ldg(&h4[(unsigned)s2 * 16u + lane]);
        float4 v3 = __ldg(&h4[(unsigned)s3 * 16u + lane]);
        a0.x += v0.x; a0.y += v0.y; a0.z += v0.z; a0.w += v0.w;
        a1.x += v1.x; a1.y += v1.y; a1.z += v1.z; a1.w += v1.w;
        a2.x += v2.x; a2.y += v2.y; a2.z += v2.z; a2.w += v2.w;
        a3.x += v3.x; a3.y += v3.y; a3.z += v3.z; a3.w += v3.w;
    }
    for (; j < e; j++) {
        int s0 = __ldg(&g_csrc[j]);
        float4 v0 = __ldg(&h4[(unsigned)s0 * 16u + lane]);
        a0.x += v0.x; a0.y += v0.y; a0.z += v0.z; a0.w += v0.w;
    }
    float4 acc;
    acc.x = (a0.x + a1.x) + (a2.x + a3.x);
    acc.y = (a0.y + a1.y) + (a2.y + a3.y);
    acc.z = (a0.z + a1.z) + (a2.z + a3.z);
    acc.w = (a0.w + a1.w) + (a2.w + a3.w);

    const float eps1 = 1.0f + __ldg(eps_l);
    float4 hv = __ldg(&h4[node * 16u + lane]);
    float4 o;
    o.x = fmaf(eps1, hv.x, acc.x);
    o.y = fmaf(eps1, hv.y, acc.y);
    o.z = fmaf(eps1, hv.z, acc.z);
    o.w = fmaf(eps1, hv.w, acc.w);
    comb4[node * 16u + lane] = o;
}

// ---------------------------------------------------------------------------
// GIN GEMM: h_out = relu(comb @ W + b). 128-node tile, 256 threads.
// A tile node-major in smem, pitch 76 floats (float4 pitch 19, odd ->
// per-node float4 A-loads are bank-conflict-free with the stride-32 node
// interleave: thread owns nodes {lane, lane+32, lane+64, lane+96}).
// Per thread: 4 nodes x 8 cols. Per 4-k step: 4 A LDS.128 + 8 W broadcast
// LDS.128 -> 128 FFMA. Direct vectorized STG (each thread owns cols cg*8..+7
// = two aligned float4 sectors of the node row).
// Dynamic smem: W 4096 + b 64 + A 128*76 = 13888 floats = 55552 B.
// ---------------------------------------------------------------------------
#define APITCH4 19

__global__ void __launch_bounds__(256)
gin_kernel(const float4* __restrict__ comb4,
           const float4* __restrict__ W4,
           const float* __restrict__ b,
           float4* __restrict__ hout4)
{
    extern __shared__ float sm[];
    float* sW = sm;              // [64][64]
    float* sB = sm + 4096;       // [64]
    float* sA = sB + 64;         // [128][76]

    const int tid = threadIdx.x;
    const int nodeBase = blockIdx.x * 128;

    float4* sW4 = reinterpret_cast<float4*>(sW);
    float4* sA4 = reinterpret_cast<float4*>(sA);

    for (int i = tid; i < 1024; i += 256) sW4[i] = __ldg(&W4[i]);
    if (tid < 64) sB[tid] = __ldg(&b[tid]);

    for (int i = tid; i < 2048; i += 256) {
        int nloc = i >> 4, d4 = i & 15;
        int node = nodeBase + nloc;
        float4 v = {0.f,0.f,0.f,0.f};
        if (node < N_NODES) v = __ldg(&comb4[node * 16 + d4]);
        sA4[nloc * APITCH4 + d4] = v;
    }
    __syncthreads();

    const int lane = tid & 31;   // nodes lane, lane+32, lane+64, lane+96
    const int cg   = tid >> 5;   // cols cg*8 .. +7 (warp-uniform)

    float acc[4][8];
    #pragma unroll
    for (int n = 0; n < 4; n++)
        #pragma unroll
        for (int c = 0; c < 8; c++)
            acc[n][c] = sB[cg * 8 + c];

    #pragma unroll 4
    for (int k4 = 0; k4 < 16; k4++) {
        float4 a[4];
        #pragma unroll
        for (int n = 0; n < 4; n++)
            a[n] = sA4[(lane + n * 32) * APITCH4 + k4];   // conflict-free
        #pragma unroll
        for (int kk = 0; kk < 4; kk++) {
            float4 w0 = sW4[(k4 * 4 + kk) * 16 + cg * 2];       // broadcast
            float4 w1 = sW4[(k4 * 4 + kk) * 16 + cg * 2 + 1];   // broadcast
            float wv[8] = {w0.x, w0.y, w0.z, w0.w, w1.x, w1.y, w1.z, w1.w};
            float av[4];
            av[0] = (kk == 0) ? a[0].x : (kk == 1) ? a[0].y : (kk == 2) ? a[0].z : a[0].w;
            av[1] = (kk == 0) ? a[1].x : (kk == 1) ? a[1].y : (kk == 2) ? a[1].z : a[1].w;
            av[2] = (kk == 0) ? a[2].x : (kk == 1) ? a[2].y : (kk == 2) ? a[2].z : a[2].w;
            av[3] = (kk == 0) ? a[3].x : (kk == 1) ? a[3].y : (kk == 2) ? a[3].z : a[3].w;
            #pragma unroll
            for (int n = 0; n < 4; n++)
                #pragma unroll
                for (int c = 0; c < 8; c++)
                    acc[n][c] = fmaf(av[n], wv[c], acc[n][c]);
        }
    }

    #pragma unroll
    for (int n = 0; n < 4; n++) {
        int node = nodeBase + lane + n * 32;
        if (node < N_NODES) {
            float4 o0, o1;
            o0.x = fmaxf(acc[n][0], 0.f); o0.y = fmaxf(acc[n][1], 0.f);
            o0.z = fmaxf(acc[n][2], 0.f); o0.w = fmaxf(acc[n][3], 0.f);
            o1.x = fmaxf(acc[n][4], 0.f); o1.y = fmaxf(acc[n][5], 0.f);
            o1.z = fmaxf(acc[n][6], 0.f); o1.w = fmaxf(acc[n][7], 0.f);
            hout4[node * 16 + cg * 2]     = o0;
            hout4[node * 16 + cg * 2 + 1] = o1;
        }
    }
}

// ---------------------------------------------------------------------------
// Graph pooling, 4 segments per graph (deterministic partials, no atomics)
// grid = NUM_GRAPHS * POOL_SEG, block 192.
// ---------------------------------------------------------------------------
__global__ void __launch_bounds__(192)
pool_kernel(const int* __restrict__ gids)
{
    const int b = blockIdx.x >> 2;
    const int seg = blockIdx.x & 3;
    const int j = threadIdx.x;

    int lo = 0, hi = N_NODES;
    while (lo < hi) { int m = (lo + hi) >> 1; if (__ldg(&gids[m]) < b) lo = m + 1; else hi = m; }
    const int start = lo;
    hi = N_NODES;
    while (lo < hi) { int m = (lo + hi) >> 1; if (__ldg(&gids[m]) < b + 1) lo = m + 1; else hi = m; }
    const int end = lo;

    const int len = end - start;
    const int s0 = start + (len * seg) / POOL_SEG;
    const int s1 = start + (len * (seg + 1)) / POOL_SEG;

    const int l = j >> 6;
    const int d = j & 63;
    const float* __restrict__ hb = g_h[l];

    float a0 = 0.f, a1 = 0.f, a2 = 0.f, a3 = 0.f;
    int n = s0;
    for (; n + 3 < s1; n += 4) {
        a0 += __ldg(&hb[(n + 0) * 64 + d]);
        a1 += __ldg(&hb[(n + 1) * 64 + d]);
        a2 += __ldg(&hb[(n + 2) * 64 + d]);
        a3 += __ldg(&hb[(n + 3) * 64 + d]);
    }
    for (; n < s1; n++) a0 += __ldg(&hb[n * 64 + d]);
    g_poolp[seg][b * (NUM_LAYERS * NODE_DIM) + j] = (a0 + a1) + (a2 + a3);
}

// ---------------------------------------------------------------------------
// Readout MLP: out = relu(g @ W1 + b1) @ W2 + b2  (sums the 4 pool partials)
// ---------------------------------------------------------------------------
__global__ void __launch_bounds__(128)
readout_kernel(const float* __restrict__ W1, const float* __restrict__ b1,
               const float* __restrict__ W2, const float* __restrict__ b2,
               float* __restrict__ out)
{
    const int b = blockIdx.x;
    const int tid = threadIdx.x;
    __shared__ float sg[NUM_LAYERS * NODE_DIM];
    __shared__ float sh[R_HID];

    for (int i = tid; i < NUM_LAYERS * NODE_DIM; i += 128) {
        int gi = b * (NUM_LAYERS * NODE_DIM) + i;
        sg[i] = (g_poolp[0][gi] + g_poolp[1][gi]) + (g_poolp[2][gi] + g_poolp[3][gi]);
    }
    __syncthreads();

    float acc = __ldg(&b1[tid]);
    #pragma unroll 8
    for (int k = 0; k < NUM_LAYERS * NODE_DIM; k++)
        acc = fmaf(sg[k], __ldg(&W1[k * R_HID + tid]), acc);
    sh[tid] = fmaxf(acc, 0.0f);
    __syncthreads();

    if (tid < R_OUT) {
        float o = __ldg(&b2[tid]);
        #pragma unroll 8
        for (int k = 0; k < R_HID; k++)
            o = fmaf(sh[k], __ldg(&W2[k * R_OUT + tid]), o);
        out[b * R_OUT + tid] = o;
    }
}

// ---------------------------------------------------------------------------
extern "C" void kernel_launch(void* const* d_in, const int* in_sizes, int n_in,
                              void* d_out, int out_size)
{
    const float* x     = (const float*)d_in[0];
    const float* gin_W = (const float*)d_in[1];
    const float* gin_b = (const float*)d_in[2];
    const float* eps   = (const float*)d_in[3];
    const float* r_W1  = (const float*)d_in[4];
    const float* r_b1  = (const float*)d_in[5];
    const float* r_W2  = (const float*)d_in[6];
    const float* r_b2  = (const float*)d_in[7];
    const int*   src   = (const int*)d_in[8];
    const int*   dst   = (const int*)d_in[9];
    const int*   gids  = (const int*)d_in[10];
    float* out = (float*)d_out;

    void* cntp = nullptr; void* combp = nullptr; void* hsym = nullptr;
    cudaGetSymbolAddress(&cntp, g_cnt);
    cudaGetSymbolAddress(&combp, g_comb);
    cudaGetSymbolAddress(&hsym, g_h);
    float* hbase = (float*)hsym;

    const int GIN_SMEM = (4096 + 64 + 128 * 76) * (int)sizeof(float);  // 55552 B
    cudaFuncSetAttribute(gin_kernel, cudaFuncAttributeMaxDynamicSharedMemorySize, GIN_SMEM);

    const int E_BLOCKS   = (N_EDGES + 255) / 256;        // 4688
    const int AGG_BLOCKS = (N_NODES * 16 + 255) / 256;   // 6250
    const int GIN_BLOCKS = (N_NODES + 127) / 128;        // 782

    // --- build CSR once per call (all phases coalesced / full-chip) ---
    cudaMemsetAsync(cntp, 0, (size_t)N_NODES * sizeof(int));
    hist_kernel<<<E_BLOCKS, 256>>>(dst);
    bsum_kernel<<<SCAN_BLOCKS, 256>>>();
    boff_kernel<<<1, 512>>>();
    rs_kernel<<<SCAN_BLOCKS, 256>>>();
    fill_kernel<<<E_BLOCKS, 256>>>(src, dst);

    for (int l = 0; l < NUM_LAYERS; l++) {
        const float* hin = (l == 0) ? x : (hbase + (size_t)(l - 1) * NN);
        agg_kernel<<<AGG_BLOCKS, 256>>>((const float4*)hin, eps + l, (float4*)combp);
        gin_kernel<<<GIN_BLOCKS, 256, GIN_SMEM>>>((const float4*)combp,
                                                  (const float4*)(gin_W + (size_t)l * 64 * 64),
                                                  gin_b + (size_t)l * 64,
                                                  (float4*)(hbase + (size_t)l * NN));
    }
    pool_kernel<<<NUM_GRAPHS * POOL_SEG, NUM_LAYERS * NODE_DIM>>>(gids);
    readout_kernel<<<NUM_GRAPHS, R_HID>>>(r_W1, r_b1, r_W2, r_b2, out);
}